// round 1
// baseline (speedup 1.0000x reference)
#include <cuda_runtime.h>

#define TPB 256
#define VEC 4
#define NPRIMES 168

__global__ __launch_bounds__(TPB)
void bwl_prime_fused(const float* __restrict__ x,
                     const float* __restrict__ kern,
                     const float* __restrict__ bias,
                     float* __restrict__ out,
                     int N, int B)
{
    // primes below 1000 (168 of them) — compile-time so every %p becomes
    // a magic-number multiply-shift, not a runtime divide.
    constexpr int PR[NPRIMES] = {
        2,3,5,7,11,13,17,19,23,29,31,37,41,43,47,53,59,61,67,71,
        73,79,83,89,97,101,103,107,109,113,127,131,137,139,149,151,157,163,167,173,
        179,181,191,193,197,199,211,223,227,229,233,239,241,251,257,263,269,271,277,281,
        283,293,307,311,313,317,331,337,347,349,353,359,367,373,379,383,389,397,401,409,
        419,421,431,433,439,443,449,457,461,463,467,479,487,491,499,503,509,521,523,541,
        547,557,563,569,571,577,587,593,599,601,607,613,617,619,631,641,643,647,653,659,
        661,673,677,683,691,701,709,719,727,733,739,743,751,757,761,769,773,787,797,809,
        811,821,823,827,829,839,853,857,859,863,877,881,883,887,907,911,919,929,937,941,
        947,953,967,971,977,983,991,997
    };
    static_assert(sizeof(PR) / sizeof(int) == NPRIMES, "prime count");

    const int k0 = (blockIdx.x * TPB + threadIdx.x) * VEC;
    if (k0 + VEC - 1 >= N) return;

    // --- Phase A: per-column weight/bias gather (once per column, in regs) ---
    float w0 = 0.f, w1 = 0.f, w2 = 0.f, w3 = 0.f;
    float a0 = 0.f, a1 = 0.f, a2 = 0.f, a3 = 0.f;

#pragma unroll
    for (int i = 0; i < NPRIMES; ++i) {
        const int p = PR[i];
        int m0 = k0 % p;                   // magic-mult mod (compile-time p)
        int m1 = m0 + 1; if (m1 == p) m1 = 0;
        int m2 = m1 + 1; if (m2 == p) m2 = 0;
        int m3 = m2 + 1; if (m3 == p) m3 = 0;
        const float* kr = kern + i * 1000;
        const float* br = bias + i * 1000;
        w0 += __ldg(kr + m0);  w1 += __ldg(kr + m1);
        w2 += __ldg(kr + m2);  w3 += __ldg(kr + m3);
        a0 += __ldg(br + m0);  a1 += __ldg(br + m1);
        a2 += __ldg(br + m2);  a3 += __ldg(br + m3);
    }

    // --- Phase B: stream all rows, coalesced float4, evict-first policy ---
    const int nv = N >> 2;
    const float4* __restrict__ xv = reinterpret_cast<const float4*>(x) + (k0 >> 2);
    float4* __restrict__ ov = reinterpret_cast<float4*>(out) + (k0 >> 2);

#pragma unroll 8
    for (int r = 0; r < B; ++r) {
        float4 xi = __ldcs(xv + (size_t)r * nv);
        float4 o;
        o.x = fmaf(xi.x, w0, a0);
        o.y = fmaf(xi.y, w1, a1);
        o.z = fmaf(xi.z, w2, a2);
        o.w = fmaf(xi.w, w3, a3);
        __stcs(ov + (size_t)r * nv, o);
    }
}

extern "C" void kernel_launch(void* const* d_in, const int* in_sizes, int n_in,
                              void* d_out, int out_size)
{
    const float* x  = (const float*)d_in[0];   // (B, N) float32
    const float* kr = (const float*)d_in[1];   // (168, 1000) float32
    const float* br = (const float*)d_in[2];   // (168, 1000) float32
    float* out = (float*)d_out;

    const int N = 524288;
    const int B = in_sizes[0] / N;             // 64

    const int grid = N / (TPB * VEC);          // 512 blocks
    bwl_prime_fused<<<grid, TPB>>>(x, kr, br, out, N, B);
}

// round 2
// speedup vs baseline: 1.5818x; 1.5818x over previous
#include <cuda_runtime.h>

#define NPRIMES 168
#define TPB 128          // threads per block (main kernel)
#define VPT 4            // columns per thread
#define COLS (TPB * VPT) // 512 columns per block
#define TABN (NPRIMES * 1000)

// Interleaved (kernel, bias) table: one LDG.64 fetches both values.
__device__ float2 g_tab[TABN];

__global__ __launch_bounds__(256)
void interleave_tab(const float* __restrict__ kern, const float* __restrict__ bias)
{
    int i = blockIdx.x * 256 + threadIdx.x;
    if (i < TABN) g_tab[i] = make_float2(kern[i], bias[i]);
}

__global__ __launch_bounds__(TPB, 8)
void bwl_prime_main(const float* __restrict__ x,
                    float* __restrict__ out,
                    int N, int B)
{
    constexpr int PR[NPRIMES] = {
        2,3,5,7,11,13,17,19,23,29,31,37,41,43,47,53,59,61,67,71,
        73,79,83,89,97,101,103,107,109,113,127,131,137,139,149,151,157,163,167,173,
        179,181,191,193,197,199,211,223,227,229,233,239,241,251,257,263,269,271,277,281,
        283,293,307,311,313,317,331,337,347,349,353,359,367,373,379,383,389,397,401,409,
        419,421,431,433,439,443,449,457,461,463,467,479,487,491,499,503,509,521,523,541,
        547,557,563,569,571,577,587,593,599,601,607,613,617,619,631,641,643,647,653,659,
        661,673,677,683,691,701,709,719,727,733,739,743,751,757,761,769,773,787,797,809,
        811,821,823,827,829,839,853,857,859,863,877,881,883,887,907,911,919,929,937,941,
        947,953,967,971,977,983,991,997
    };

    __shared__ float w_s[COLS];
    __shared__ float b_s[COLS];

    const int t  = threadIdx.x;
    const int k0 = blockIdx.x * COLS;
    const int k  = k0 + t;          // column for v=0; v steps by TPB

    // ---- Phase A: gather w/b for this block's 512 columns ----
    // Lane t reads table index derived from column k0 + v*TPB + t:
    // consecutive lanes -> consecutive mod values -> coalesced LDG.64.
    float w0 = 0.f, w1 = 0.f, w2 = 0.f, w3 = 0.f;
    float a0 = 0.f, a1 = 0.f, a2 = 0.f, a3 = 0.f;

#pragma unroll
    for (int i = 0; i < NPRIMES; ++i) {
        const int p = PR[i];
        const int C = TPB % p;            // compile-time constant
        const float2* __restrict__ row = g_tab + i * 1000;

        int m = k % p;                    // magic-mult mod (constexpr p)
        float2 e0 = __ldg(row + m);
        m += C; if (m >= p) m -= p;
        float2 e1 = __ldg(row + m);
        m += C; if (m >= p) m -= p;
        float2 e2 = __ldg(row + m);
        m += C; if (m >= p) m -= p;
        float2 e3 = __ldg(row + m);

        w0 += e0.x; a0 += e0.y;
        w1 += e1.x; a1 += e1.y;
        w2 += e2.x; a2 += e2.y;
        w3 += e3.x; a3 += e3.y;
    }

    w_s[0 * TPB + t] = w0;  b_s[0 * TPB + t] = a0;
    w_s[1 * TPB + t] = w1;  b_s[1 * TPB + t] = a1;
    w_s[2 * TPB + t] = w2;  b_s[2 * TPB + t] = a2;
    w_s[3 * TPB + t] = w3;  b_s[3 * TPB + t] = a3;
    __syncthreads();

    // ---- Phase B: stream all rows for this block's columns ----
    const int c = t * 4;                       // 0..508, float4-aligned
    const float4 wv = *reinterpret_cast<const float4*>(&w_s[c]);
    const float4 bv = *reinterpret_cast<const float4*>(&b_s[c]);

    const int nv = N >> 2;
    const float4* __restrict__ xv = reinterpret_cast<const float4*>(x)   + ((k0 + c) >> 2);
    float4* __restrict__       ov = reinterpret_cast<float4*>(out)       + ((k0 + c) >> 2);

#pragma unroll 8
    for (int r = 0; r < B; ++r) {
        float4 xi = __ldcs(xv + (size_t)r * nv);
        float4 o;
        o.x = fmaf(xi.x, wv.x, bv.x);
        o.y = fmaf(xi.y, wv.y, bv.y);
        o.z = fmaf(xi.z, wv.z, bv.z);
        o.w = fmaf(xi.w, wv.w, bv.w);
        __stcs(ov + (size_t)r * nv, o);
    }
}

extern "C" void kernel_launch(void* const* d_in, const int* in_sizes, int n_in,
                              void* d_out, int out_size)
{
    const float* x  = (const float*)d_in[0];   // (B, N) float32
    const float* kr = (const float*)d_in[1];   // (168, 1000) float32
    const float* br = (const float*)d_in[2];   // (168, 1000) float32
    float* out = (float*)d_out;

    const int N = 524288;
    const int B = in_sizes[0] / N;             // 64

    interleave_tab<<<(TABN + 255) / 256, 256>>>(kr, br);

    const int grid = N / COLS;                 // 1024 blocks
    bwl_prime_main<<<grid, TPB>>>(x, out, N, B);
}

// round 3
// speedup vs baseline: 1.7458x; 1.1037x over previous
#include <cuda_runtime.h>

#define NPRIMES 168
#define TPB 128
#define VPT 4
#define COLS (TPB * VPT)   // 512 columns per block
#define TABN (NPRIMES * 1000)

// Interleaved (kernel, bias) table: one LDG.64 fetches both values.
__device__ float2 g_tab[TABN];

// Per-prime descriptor, built entirely at compile time into constant memory:
//  magic = floor(2^32 / p) + 1  -> m = k - p * umulhi(k, magic) == k % p
//  (exact for k < 2^20, p < 2^10; for p=2 magic=2^31 exact)
//  c = TPB % p  (mod increment when stepping a column by TPB)
struct PInfo { unsigned magic; int p; int c; };

#define PRIME_LIST \
 X(2) X(3) X(5) X(7) X(11) X(13) X(17) X(19) X(23) X(29) \
 X(31) X(37) X(41) X(43) X(47) X(53) X(59) X(61) X(67) X(71) \
 X(73) X(79) X(83) X(89) X(97) X(101) X(103) X(107) X(109) X(113) \
 X(127) X(131) X(137) X(139) X(149) X(151) X(157) X(163) X(167) X(173) \
 X(179) X(181) X(191) X(193) X(197) X(199) X(211) X(223) X(227) X(229) \
 X(233) X(239) X(241) X(251) X(257) X(263) X(269) X(271) X(277) X(281) \
 X(283) X(293) X(307) X(311) X(313) X(317) X(331) X(337) X(347) X(349) \
 X(353) X(359) X(367) X(373) X(379) X(383) X(389) X(397) X(401) X(409) \
 X(419) X(421) X(431) X(433) X(439) X(443) X(449) X(457) X(461) X(463) \
 X(467) X(479) X(487) X(491) X(499) X(503) X(509) X(521) X(523) X(541) \
 X(547) X(557) X(563) X(569) X(571) X(577) X(587) X(593) X(599) X(601) \
 X(607) X(613) X(617) X(619) X(631) X(641) X(643) X(647) X(653) X(659) \
 X(661) X(673) X(677) X(683) X(691) X(701) X(709) X(719) X(727) X(733) \
 X(739) X(743) X(751) X(757) X(761) X(769) X(773) X(787) X(797) X(809) \
 X(811) X(821) X(823) X(827) X(829) X(839) X(853) X(857) X(859) X(863) \
 X(877) X(881) X(883) X(887) X(907) X(911) X(919) X(929) X(937) X(941) \
 X(947) X(953) X(967) X(971) X(977) X(983) X(991) X(997)

__constant__ PInfo C_PI[NPRIMES] = {
#define X(p) { 0xFFFFFFFFu / (unsigned)(p) + 1u, (p), TPB % (p) },
  PRIME_LIST
#undef X
};

__global__ __launch_bounds__(256)
void interleave_tab(const float* __restrict__ kern, const float* __restrict__ bias)
{
    int i = blockIdx.x * 256 + threadIdx.x;
    if (i < TABN) g_tab[i] = make_float2(kern[i], bias[i]);
}

__global__ __launch_bounds__(TPB, 10)
void bwl_prime_main(const float* __restrict__ x,
                    float* __restrict__ out,
                    int N, int B)
{
    __shared__ float w_s[COLS];
    __shared__ float b_s[COLS];

    const int t  = threadIdx.x;
    const int k0 = blockIdx.x * COLS;
    const unsigned k = (unsigned)(k0 + t);   // column for v=0; v steps by TPB

    // ---- Phase A: gather w/b for this block's 512 columns ----
    float w0 = 0.f, w1 = 0.f, w2 = 0.f, w3 = 0.f;
    float a0 = 0.f, a1 = 0.f, a2 = 0.f, a3 = 0.f;

    const float2* __restrict__ row = g_tab;

#pragma unroll 2
    for (int i = 0; i < NPRIMES; ++i) {
        const PInfo pi = C_PI[i];           // uniform constant-memory read
        const int p = pi.p;
        const int c = pi.c;

        int m = (int)(k - (unsigned)p * __umulhi(k, pi.magic));  // k % p

        float2 e0 = __ldg(row + m);
        m += c; if (m >= p) m -= p;
        float2 e1 = __ldg(row + m);
        m += c; if (m >= p) m -= p;
        float2 e2 = __ldg(row + m);
        m += c; if (m >= p) m -= p;
        float2 e3 = __ldg(row + m);

        w0 += e0.x; a0 += e0.y;
        w1 += e1.x; a1 += e1.y;
        w2 += e2.x; a2 += e2.y;
        w3 += e3.x; a3 += e3.y;

        row += 1000;
    }

    w_s[0 * TPB + t] = w0;  b_s[0 * TPB + t] = a0;
    w_s[1 * TPB + t] = w1;  b_s[1 * TPB + t] = a1;
    w_s[2 * TPB + t] = w2;  b_s[2 * TPB + t] = a2;
    w_s[3 * TPB + t] = w3;  b_s[3 * TPB + t] = a3;
    __syncthreads();

    // ---- Phase B: stream all rows for this block's columns ----
    const int c4 = t * 4;                                  // 0..508
    const float4 wv = *reinterpret_cast<const float4*>(&w_s[c4]);
    const float4 bv = *reinterpret_cast<const float4*>(&b_s[c4]);

    const size_t nv = (size_t)(N >> 2);
    const float4* __restrict__ xv = reinterpret_cast<const float4*>(x)  + ((k0 + c4) >> 2);
    float4* __restrict__       ov = reinterpret_cast<float4*>(out)      + ((k0 + c4) >> 2);

#pragma unroll 8
    for (int r = 0; r < B; ++r) {
        float4 xi = __ldcs(xv);
        float4 o;
        o.x = fmaf(xi.x, wv.x, bv.x);
        o.y = fmaf(xi.y, wv.y, bv.y);
        o.z = fmaf(xi.z, wv.z, bv.z);
        o.w = fmaf(xi.w, wv.w, bv.w);
        __stcs(ov, o);
        xv += nv;
        ov += nv;
    }
}

extern "C" void kernel_launch(void* const* d_in, const int* in_sizes, int n_in,
                              void* d_out, int out_size)
{
    const float* x  = (const float*)d_in[0];   // (B, N) float32
    const float* kr = (const float*)d_in[1];   // (168, 1000) float32
    const float* br = (const float*)d_in[2];   // (168, 1000) float32
    float* out = (float*)d_out;

    const int N = 524288;
    const int B = in_sizes[0] / N;             // 64

    interleave_tab<<<(TABN + 255) / 256, 256>>>(kr, br);

    const int grid = N / COLS;                 // 1024 blocks
    bwl_prime_main<<<grid, TPB>>>(x, out, N, B);
}

// round 4
// speedup vs baseline: 2.2253x; 1.2747x over previous
#include <cuda_runtime.h>

#define NPRIMES 168
#define TPB 256
#define VPT 2
#define COLS (TPB * VPT)   // 512 columns per block
#define TABN (NPRIMES * 1000)

// Interleaved (kernel, bias) table: one LDG.64 fetches both values.
__device__ float2 g_tab[TABN];

// Per-prime descriptor, compile-time, in constant memory:
//  magic = floor(2^32 / p) + 1  -> m = k - p * umulhi(k, magic) == k % p
//  (exact for k < 2^20, p < 2^10)
//  c = TPB % p  (mod increment when stepping a column by TPB)
struct PInfo { unsigned magic; int p; int c; };

#define PRIME_LIST \
 X(2) X(3) X(5) X(7) X(11) X(13) X(17) X(19) X(23) X(29) \
 X(31) X(37) X(41) X(43) X(47) X(53) X(59) X(61) X(67) X(71) \
 X(73) X(79) X(83) X(89) X(97) X(101) X(103) X(107) X(109) X(113) \
 X(127) X(131) X(137) X(139) X(149) X(151) X(157) X(163) X(167) X(173) \
 X(179) X(181) X(191) X(193) X(197) X(199) X(211) X(223) X(227) X(229) \
 X(233) X(239) X(241) X(251) X(257) X(263) X(269) X(271) X(277) X(281) \
 X(283) X(293) X(307) X(311) X(313) X(317) X(331) X(337) X(347) X(349) \
 X(353) X(359) X(367) X(373) X(379) X(383) X(389) X(397) X(401) X(409) \
 X(419) X(421) X(431) X(433) X(439) X(443) X(449) X(457) X(461) X(463) \
 X(467) X(479) X(487) X(491) X(499) X(503) X(509) X(521) X(523) X(541) \
 X(547) X(557) X(563) X(569) X(571) X(577) X(587) X(593) X(599) X(601) \
 X(607) X(613) X(617) X(619) X(631) X(641) X(643) X(647) X(653) X(659) \
 X(661) X(673) X(677) X(683) X(691) X(701) X(709) X(719) X(727) X(733) \
 X(739) X(743) X(751) X(757) X(761) X(769) X(773) X(787) X(797) X(809) \
 X(811) X(821) X(823) X(827) X(829) X(839) X(853) X(857) X(859) X(863) \
 X(877) X(881) X(883) X(887) X(907) X(911) X(919) X(929) X(937) X(941) \
 X(947) X(953) X(967) X(971) X(977) X(983) X(991) X(997)

__constant__ PInfo C_PI[NPRIMES] = {
#define X(p) { 0xFFFFFFFFu / (unsigned)(p) + 1u, (p), TPB % (p) },
  PRIME_LIST
#undef X
};

__global__ __launch_bounds__(256)
void interleave_tab(const float* __restrict__ kern, const float* __restrict__ bias)
{
    int i = blockIdx.x * 256 + threadIdx.x;
    if (i < TABN) g_tab[i] = make_float2(kern[i], bias[i]);
}

__global__ __launch_bounds__(TPB, 6)
void bwl_prime_main(const float* __restrict__ x,
                    float* __restrict__ out,
                    int N, int B)
{
    __shared__ float w_s[COLS];
    __shared__ float b_s[COLS];

    const int t  = threadIdx.x;
    const int k0 = blockIdx.x * COLS;
    const unsigned k = (unsigned)(k0 + t);   // column for v=0; v=1 adds TPB

    // ---- Phase A: gather w/b for this block's 512 columns ----
    // Lane-consecutive table indices -> coalesced LDG.64 (2 lines/warp).
    float w0 = 0.f, w1 = 0.f;
    float a0 = 0.f, a1 = 0.f;

    const float2* __restrict__ row = g_tab;

#pragma unroll 4
    for (int i = 0; i < NPRIMES; ++i) {
        const PInfo pi = C_PI[i];           // uniform constant read
        const int p = pi.p;

        int m = (int)(k - (unsigned)p * __umulhi(k, pi.magic));  // k % p
        float2 e0 = __ldg(row + m);
        m += pi.c; if (m >= p) m -= p;
        float2 e1 = __ldg(row + m);

        w0 += e0.x; a0 += e0.y;
        w1 += e1.x; a1 += e1.y;

        row += 1000;
    }

    w_s[t]       = w0;  b_s[t]       = a0;
    w_s[TPB + t] = w1;  b_s[TPB + t] = a1;
    __syncthreads();

    // ---- Phase B: stream rows; 2 row-halves x 128 float4-columns ----
    const int col4  = t & 127;              // float4 column within block
    const int rbeg  = (t >> 7) * (B >> 1);  // 0 or B/2
    const int rend  = rbeg + (B >> 1);

    const float4 wv = *reinterpret_cast<const float4*>(&w_s[col4 * 4]);
    const float4 bv = *reinterpret_cast<const float4*>(&b_s[col4 * 4]);

    const size_t nv = (size_t)(N >> 2);
    const float4* __restrict__ xv = reinterpret_cast<const float4*>(x)
                                    + (size_t)rbeg * nv + (k0 >> 2) + col4;
    float4* __restrict__       ov = reinterpret_cast<float4*>(out)
                                    + (size_t)rbeg * nv + (k0 >> 2) + col4;

#pragma unroll 8
    for (int r = rbeg; r < rend; ++r) {
        float4 xi = __ldcs(xv);
        float4 o;
        o.x = fmaf(xi.x, wv.x, bv.x);
        o.y = fmaf(xi.y, wv.y, bv.y);
        o.z = fmaf(xi.z, wv.z, bv.z);
        o.w = fmaf(xi.w, wv.w, bv.w);
        __stcs(ov, o);
        xv += nv;
        ov += nv;
    }
}

extern "C" void kernel_launch(void* const* d_in, const int* in_sizes, int n_in,
                              void* d_out, int out_size)
{
    const float* x  = (const float*)d_in[0];   // (B, N) float32
    const float* kr = (const float*)d_in[1];   // (168, 1000) float32
    const float* br = (const float*)d_in[2];   // (168, 1000) float32
    float* out = (float*)d_out;

    const int N = 524288;
    const int B = in_sizes[0] / N;             // 64

    interleave_tab<<<(TABN + 255) / 256, 256>>>(kr, br);

    const int grid = N / COLS;                 // 1024 blocks
    bwl_prime_main<<<grid, TPB>>>(x, out, N, B);
}

// round 5
// speedup vs baseline: 2.6269x; 1.1805x over previous
#include <cuda_runtime.h>

#define NPRIMES 168
#define TPB 256
#define COLS 256          // 1 column per thread
#define TABN (NPRIMES * 1000)

// Interleaved (kernel, bias) table: one LDG.64 fetches both values.
__device__ float2 g_tab[TABN];

// Per-prime magic-mod descriptor (compile-time, constant memory):
//  magic = floor(2^32/p)+1  ->  k % p == k - p*umulhi(k, magic)   (k<2^20)
struct PInfo { unsigned magic; int p; };

#define PRIME_LIST \
 X(2) X(3) X(5) X(7) X(11) X(13) X(17) X(19) X(23) X(29) \
 X(31) X(37) X(41) X(43) X(47) X(53) X(59) X(61) X(67) X(71) \
 X(73) X(79) X(83) X(89) X(97) X(101) X(103) X(107) X(109) X(113) \
 X(127) X(131) X(137) X(139) X(149) X(151) X(157) X(163) X(167) X(173) \
 X(179) X(181) X(191) X(193) X(197) X(199) X(211) X(223) X(227) X(229) \
 X(233) X(239) X(241) X(251) X(257) X(263) X(269) X(271) X(277) X(281) \
 X(283) X(293) X(307) X(311) X(313) X(317) X(331) X(337) X(347) X(349) \
 X(353) X(359) X(367) X(373) X(379) X(383) X(389) X(397) X(401) X(409) \
 X(419) X(421) X(431) X(433) X(439) X(443) X(449) X(457) X(461) X(463) \
 X(467) X(479) X(487) X(491) X(499) X(503) X(509) X(521) X(523) X(541) \
 X(547) X(557) X(563) X(569) X(571) X(577) X(587) X(593) X(599) X(601) \
 X(607) X(613) X(617) X(619) X(631) X(641) X(643) X(647) X(653) X(659) \
 X(661) X(673) X(677) X(683) X(691) X(701) X(709) X(719) X(727) X(733) \
 X(739) X(743) X(751) X(757) X(761) X(769) X(773) X(787) X(797) X(809) \
 X(811) X(821) X(823) X(827) X(829) X(839) X(853) X(857) X(859) X(863) \
 X(877) X(881) X(883) X(887) X(907) X(911) X(919) X(929) X(937) X(941) \
 X(947) X(953) X(967) X(971) X(977) X(983) X(991) X(997)

__constant__ PInfo C_PI[NPRIMES] = {
#define X(p) { 0xFFFFFFFFu / (unsigned)(p) + 1u, (p) },
  PRIME_LIST
#undef X
};

__global__ __launch_bounds__(256)
void interleave_tab(const float* __restrict__ kern, const float* __restrict__ bias)
{
    int i = blockIdx.x * 256 + threadIdx.x;
    if (i < TABN) g_tab[i] = make_float2(kern[i], bias[i]);
}

__global__ __launch_bounds__(TPB, 8)
void bwl_prime_main(const float* __restrict__ x,
                    float* __restrict__ out,
                    int N, int B)
{
    __shared__ float w_s[COLS];
    __shared__ float b_s[COLS];

    const int t  = threadIdx.x;
    const int k0 = blockIdx.x * COLS;
    const unsigned k = (unsigned)(k0 + t);     // this thread's column

    // ---- Phase A: gather w/b for one column per thread ----
    // Lane-consecutive residues -> coalesced LDG.64 (2 lines/warp).
    float w = 0.f, a = 0.f;
    const float2* __restrict__ row = g_tab;

#pragma unroll 8
    for (int i = 0; i < NPRIMES; ++i) {
        const PInfo pi = C_PI[i];               // uniform constant read
        int m = (int)(k - (unsigned)pi.p * __umulhi(k, pi.magic));  // k % p
        float2 e = __ldg(row + m);
        w += e.x; a += e.y;
        row += 1000;
    }

    w_s[t] = w;  b_s[t] = a;
    __syncthreads();

    // ---- Phase B: stream; 4 row-groups x 64 float4-columns ----
    const int col4 = t & 63;                    // float4 column within block
    const int rpg  = B >> 2;                    // rows per group (16)
    const int rbeg = (t >> 6) * rpg;

    const float4 wv = *reinterpret_cast<const float4*>(&w_s[col4 * 4]);
    const float4 bv = *reinterpret_cast<const float4*>(&b_s[col4 * 4]);

    const size_t nv = (size_t)(N >> 2);
    const float4* __restrict__ xv = reinterpret_cast<const float4*>(x)
                                    + (size_t)rbeg * nv + (k0 >> 2) + col4;
    float4* __restrict__       ov = reinterpret_cast<float4*>(out)
                                    + (size_t)rbeg * nv + (k0 >> 2) + col4;

#pragma unroll 8
    for (int r = 0; r < rpg; ++r) {
        float4 xi = __ldcs(xv);
        float4 o;
        o.x = fmaf(xi.x, wv.x, bv.x);
        o.y = fmaf(xi.y, wv.y, bv.y);
        o.z = fmaf(xi.z, wv.z, bv.z);
        o.w = fmaf(xi.w, wv.w, bv.w);
        __stcs(ov, o);
        xv += nv;
        ov += nv;
    }
}

extern "C" void kernel_launch(void* const* d_in, const int* in_sizes, int n_in,
                              void* d_out, int out_size)
{
    const float* x  = (const float*)d_in[0];   // (B, N) float32
    const float* kr = (const float*)d_in[1];   // (168, 1000) float32
    const float* br = (const float*)d_in[2];   // (168, 1000) float32
    float* out = (float*)d_out;

    const int N = 524288;
    const int B = in_sizes[0] / N;             // 64

    interleave_tab<<<(TABN + 255) / 256, 256>>>(kr, br);

    const int grid = N / COLS;                 // 2048 blocks -> ~2 waves
    bwl_prime_main<<<grid, TPB>>>(x, out, N, B);
}